// round 13
// baseline (speedup 1.0000x reference)
#include <cuda_runtime.h>
#include <cuda_fp16.h>
#include <cstdint>
#include <cstddef>

// ---------------- problem shape ----------------
#define B_  256
#define F_  784
#define T_  128
#define U_  2048
#define KP  832            // K padded to 13*64 (zeros beyond 784 contribute 0)
#define KC  64             // k per chunk
#define NCH 13             // KP/KC
#define NT  128            // u-tile per CTA

#define ALPHA_  0.9f
#define BETA_   0.85f
#define THRESH_ 1.0f
#define SPLIT_SCALE 2048.0f
#define INV_SCALE (1.0f / 2048.0f)

// smem stage layout:
//   A0,A1: [64 k rows][136 halfs] (128 t data + 8 pad) = 17408 B each
//          row stride 272B -> 68 words mod 32 = 4: 8-row ldmatrix groups conflict-free
//   B0,B1: [128 u rows][72 halfs] (64 k data + 8 pad)  = 18432 B each (R11 layout)
#define A_ROWH  136
#define A_ARR   (64 * A_ROWH * 2)     // 17408
#define B_ROWH  72
#define B_ARR   (128 * B_ROWH * 2)    // 18432
#define BOFF0   (2 * A_ARR)           // 34816
#define STAGE_B (2 * A_ARR + 2 * B_ARR)   // 71680
#define SMEM_TOTAL (2 * STAGE_B)      // 143360 (epilogue Cs 128*132*4=67584 aliases)

// ---------------- scratch (device globals; allocation-free rule) ----------
// X splits stored in ORIGINAL [b][f][t] order (no transpose needed in split).
__device__ __half X0d[B_][KP][T_];    // 54.5 MB
__device__ __half X1d[B_][KP][T_];    // 54.5 MB  residual*2048
__device__ __half W0d[U_][KP];        // 3.4 MB   K-major
__device__ __half W1d[U_][KP];        // 3.4 MB

// ---------------- PTX helpers (all baseline ISA -> compute_103 OK) --------
__device__ __forceinline__ void cp_async16(uint32_t saddr, const void* g) {
    asm volatile("cp.async.cg.shared.global [%0], [%1], 16;"
                 :: "r"(saddr), "l"(g) : "memory");
}
__device__ __forceinline__ void cp_commit() {
    asm volatile("cp.async.commit_group;" ::: "memory");
}
__device__ __forceinline__ void cp_wait1() {
    asm volatile("cp.async.wait_group 1;" ::: "memory");
}
__device__ __forceinline__ void cp_wait0() {
    asm volatile("cp.async.wait_group 0;" ::: "memory");
}
// non-trans ldmatrix x4 (B operand)
__device__ __forceinline__ void ldsm4(uint32_t* r, uint32_t addr) {
    asm volatile("ldmatrix.sync.aligned.m8n8.x4.shared.b16 {%0,%1,%2,%3}, [%4];"
                 : "=r"(r[0]), "=r"(r[1]), "=r"(r[2]), "=r"(r[3]) : "r"(addr));
}
// trans ldmatrix x4 (A operand from [k][t]-major storage)
__device__ __forceinline__ void ldsm4t(uint32_t* r, uint32_t addr) {
    asm volatile("ldmatrix.sync.aligned.m8n8.x4.trans.shared.b16 {%0,%1,%2,%3}, [%4];"
                 : "=r"(r[0]), "=r"(r[1]), "=r"(r[2]), "=r"(r[3]) : "r"(addr));
}
__device__ __forceinline__ void mma16816(float* c, const uint32_t* a, const uint32_t* b) {
    asm volatile(
        "mma.sync.aligned.m16n8k16.row.col.f32.f16.f16.f32 "
        "{%0,%1,%2,%3}, {%4,%5,%6,%7}, {%8,%9}, {%0,%1,%2,%3};"
        : "+f"(c[0]), "+f"(c[1]), "+f"(c[2]), "+f"(c[3])
        : "r"(a[0]), "r"(a[1]), "r"(a[2]), "r"(a[3]), "r"(b[0]), "r"(b[1]));
}
__device__ __forceinline__ uint32_t hmul2(uint32_t a, uint32_t s) {
    uint32_t d;
    asm("mul.f16x2 %0, %1, %2;" : "=r"(d) : "r"(a), "r"(s));
    return d;
}
#define SCALE_A_2M5 0x28002800u   // half2(2^-5, 2^-5)
#define SCALE_B_2M6 0x24002400u   // half2(2^-6, 2^-6)
__device__ __forceinline__ uint32_t s2u(const void* p) {
    return (uint32_t)__cvta_generic_to_shared(p);
}

// ---------------- split precompute ----------------
// Pure streaming: x[b][f][t] -> X0d/X1d[b][f][t]; per-element math identical
// to prior rounds (bit-exact values). f in [784,832) zero-filled.
__global__ void split_x_stream(const float* __restrict__ x) {
    const int b    = blockIdx.y;
    const int gid2 = blockIdx.x * 256 + threadIdx.x;   // 0..26623
    const int f    = gid2 >> 5;                        // 0..831
    const int tq   = gid2 & 31;                        // float4 quad along t
    float4 v = make_float4(0.f, 0.f, 0.f, 0.f);
    if (f < F_) v = *(const float4*)&x[((size_t)b * F_ + f) * T_ + tq * 4];
    const __half h0x = __float2half_rn(v.x);
    const __half h0y = __float2half_rn(v.y);
    const __half h0z = __float2half_rn(v.z);
    const __half h0w = __float2half_rn(v.w);
    const __half h1x = __float2half_rn((v.x - __half2float(h0x)) * SPLIT_SCALE);
    const __half h1y = __float2half_rn((v.y - __half2float(h0y)) * SPLIT_SCALE);
    const __half h1z = __float2half_rn((v.z - __half2float(h0z)) * SPLIT_SCALE);
    const __half h1w = __float2half_rn((v.w - __half2float(h0w)) * SPLIT_SCALE);
    __half2 p0[2] = { __halves2half2(h0x, h0y), __halves2half2(h0z, h0w) };
    __half2 p1[2] = { __halves2half2(h1x, h1y), __halves2half2(h1z, h1w) };
    *(uint2*)&X0d[b][f][tq * 4] = *(uint2*)p0;
    *(uint2*)&X1d[b][f][tq * 4] = *(uint2*)p1;
}
// W[f][u] -> W0/W1 [u][f] (K-major; unchanged bit-exact math, zero-pads f>=784)
__global__ void split_w_kernel(const float* __restrict__ W) {
    __shared__ float tile[32][33];
    const int f0 = blockIdx.x * 32;
    const int u0 = blockIdx.y * 32;
    const int tx = threadIdx.x, ty = threadIdx.y;
    const int tid = ty * 32 + tx;
    for (int i = ty; i < 32; i += 8) {
        const int f = f0 + i;
        float v = 0.f;
        if (f < F_) v = W[(size_t)f * U_ + u0 + tx];
        tile[i][tx] = v;
    }
    __syncthreads();
    for (int idx = tid; idx < 32 * 16; idx += 256) {
        const int i = idx >> 4;           // u row
        const int j = idx & 15;           // f pair
        const int u = u0 + i;
        const int f = f0 + 2 * j;
        const float v0 = tile[2 * j][i];
        const float v1 = tile[2 * j + 1][i];
        const __half h0a = __float2half_rn(v0);
        const __half h1a = __float2half_rn((v0 - __half2float(h0a)) * SPLIT_SCALE);
        const __half h0b = __float2half_rn(v1);
        const __half h1b = __float2half_rn((v1 - __half2float(h0b)) * SPLIT_SCALE);
        *(__half2*)&W0d[u][f] = __halves2half2(h0a, h0b);
        *(__half2*)&W1d[u][f] = __halves2half2(h1a, h1b);
    }
}

// ---------------- chunk loader: 8 cp.async16 per thread (512 threads) -----
// A arrays: 64 k-rows x 16 units (256B data/row). B arrays: 128 u-rows x 8 units.
__device__ __forceinline__ void load_chunk(uint32_t sb, int stage, int p,
                                           int b, int u0, int tid) {
    const uint32_t st = sb + stage * STAGE_B;
    const int k0 = p * KC;
#pragma unroll
    for (int q = 0; q < 2; ++q) {                    // A0 / A1
        const __half* src = q ? &X1d[b][k0][0] : &X0d[b][k0][0];
#pragma unroll
        for (int i = 0; i < 2; ++i) {
            const int u_  = tid + 512 * i;           // 0..1023
            const int row = u_ >> 4;                 // k row 0..63
            const int c   = u_ & 15;                 // 16B unit (t)
            cp_async16(st + q * A_ARR + row * (A_ROWH * 2) + c * 16,
                       (const char*)src + (size_t)row * (T_ * 2) + c * 16);
        }
    }
#pragma unroll
    for (int q = 0; q < 2; ++q) {                    // B0 / B1
        const __half* src = q ? &W1d[u0][k0] : &W0d[u0][k0];
#pragma unroll
        for (int i = 0; i < 2; ++i) {
            const int u_  = tid + 512 * i;           // 0..1023
            const int row = u_ >> 3;                 // u row 0..127
            const int c   = u_ & 7;                  // 16B unit (k)
            cp_async16(st + BOFF0 + q * B_ARR + row * (B_ROWH * 2) + c * 16,
                       (const char*)src + (size_t)row * (KP * 2) + c * 16);
        }
    }
}

// ---------------- fused mma.sync GEMM + LIF scan ----------------
// 512 threads, 16 warps: warp tile m16 x n64 (m0 = (wid>>1)*16, n0 = (wid&1)*64).
// Per-accumulator k16 order ascending, term order (a0b0; a0b1,a1b0,a1m*b1m)
// unchanged -> bit-identical to R11 (rel_err must be exactly 0.000991695).
__global__ __launch_bounds__(512, 1)
void snn_mma_kernel(float* __restrict__ out)
{
    extern __shared__ __align__(128) char smem[];
    const uint32_t sb = s2u(smem);
    const int tid = threadIdx.x;
    const int wid = tid >> 5;
    const int lid = tid & 31;
    const int u0  = blockIdx.x * NT;
    const int b   = blockIdx.y;
    const int m0  = (wid >> 1) * 16;          // 8 M-groups
    const int n0  = (wid & 1) * 64;           // 2 N-groups

    // accumulators: 8 n-tiles x 4 regs, two sets
    float acc0[32], acc1[32];
#pragma unroll
    for (int i = 0; i < 32; ++i) { acc0[i] = 0.f; acc1[i] = 0.f; }

    // A trans-ldmatrix lane addressing (A stored [k][t]):
    //   matrix i = lid>>3:  0:(k0-7,m0-7) 1:(k0-7,m8-15) 2:(k8-15,m0-7) 3:(k8-15,m8-15)
    const int a_krow = ((lid >> 4) << 3) + (lid & 7);       // +8 for matrices 2,3
    const int a_colb = (m0 + ((lid >> 3) & 1) * 8) * 2;     // byte col (t)
    // B non-trans lane addressing (unchanged from R11)
    const int brbase = (lid & 7) + ((lid & 16) ? 8 : 0);
    const int bc = (lid >> 3) & 1;

    load_chunk(sb, 0, 0, b, u0, tid);
    cp_commit();

    for (int p = 0; p < NCH; ++p) {
        const int s = p & 1;
        if (p + 1 < NCH) { load_chunk(sb, s ^ 1, p + 1, b, u0, tid); cp_commit(); }
        if (p + 1 < NCH) cp_wait1(); else cp_wait0();   // chunk p landed (mine)
        __syncthreads();                                 // everyone's landed

        const uint32_t st = sb + s * STAGE_B;
#pragma unroll
        for (int ks = 0; ks < 4; ++ks) {                 // four k16 steps
            uint32_t a0f[4], a1f[4], a1m[4];
            const uint32_t aoff = st + (ks * 16 + a_krow) * (A_ROWH * 2) + a_colb;
            ldsm4t(a0f, aoff);                           // A0 (trans)
            ldsm4t(a1f, aoff + A_ARR);                   // A1 (residual*2048)
#pragma unroll
            for (int i = 0; i < 4; ++i) a1m[i] = hmul2(a1f[i], SCALE_A_2M5);
#pragma unroll
            for (int j = 0; j < 4; ++j) {                // warp's 4 n-pairs
                uint32_t b0f[4], b1f[4], b1m[4];
                const uint32_t boff = st + BOFF0
                    + (n0 + j * 16 + brbase) * (B_ROWH * 2) + ks * 32 + bc * 16;
                ldsm4(b0f, boff);                        // W0
                ldsm4(b1f, boff + B_ARR);                // W1 (residual*2048)
#pragma unroll
                for (int i = 0; i < 4; ++i) b1m[i] = hmul2(b1f[i], SCALE_B_2M6);
                float* c0a = acc0 + (2 * j) * 4;
                float* c1a = acc1 + (2 * j) * 4;
                float* c0b = acc0 + (2 * j + 1) * 4;
                float* c1b = acc1 + (2 * j + 1) * 4;
                // n-tile 2j (frag regs [0],[1])
                mma16816(c0a, a0f, b0f);
                mma16816(c1a, a0f, b1f);
                mma16816(c1a, a1f, b0f);
                mma16816(c1a, a1m, b1m);
                // n-tile 2j+1 (frag regs [2],[3])
                mma16816(c0b, a0f, b0f + 2);
                mma16816(c1b, a0f, b1f + 2);
                mma16816(c1b, a1f, b0f + 2);
                mma16816(c1b, a1m, b1m + 2);
            }
        }
        if (p + 1 < NCH) __syncthreads();   // stage s reads done before iter p+1
    }

    // ---- epilogue: combine splits, park h in smem (aliases stages) ----
    __syncthreads();
    float* Cs = (float*)smem;               // [128][132]
    const int g  = lid >> 2;
    const int c2 = (lid & 3) * 2;
#pragma unroll
    for (int nt = 0; nt < 8; ++nt) {
        const int col = n0 + nt * 8 + c2;
        const float* p0 = acc0 + nt * 4;
        const float* p1 = acc1 + nt * 4;
        float2 v0 = { p0[0] + p1[0] * INV_SCALE, p0[1] + p1[1] * INV_SCALE };
        float2 v1 = { p0[2] + p1[2] * INV_SCALE, p0[3] + p1[3] * INV_SCALE };
        *(float2*)&Cs[(m0 + g) * 132 + col]     = v0;
        *(float2*)&Cs[(m0 + g + 8) * 132 + col] = v1;
    }
    __syncthreads();

    // ---- LIF scan over t; thread = u column (threads 0..127) ----
    if (tid < NT) {
        float* op = out + (size_t)b * T_ * U_ + u0 + tid;
        float syn = 0.f, mem = 0.f;
#pragma unroll 4
        for (int t = 0; t < T_; ++t) {
            const float h = Cs[t * 132 + tid];
            syn = ALPHA_ * syn + h;           // synaptic current decay
            mem = BETA_  * mem + syn;         // membrane decay
            const float spk = (mem - THRESH_ > 0.f) ? 1.f : 0.f;
            mem -= spk * THRESH_;             // soft reset
            op[(size_t)t * U_] = spk;
        }
    }
}

// ---------------- launch ----------------
extern "C" void kernel_launch(void* const* d_in, const int* in_sizes, int n_in,
                              void* d_out, int out_size) {
    (void)in_sizes; (void)n_in; (void)out_size;
    const float* x = (const float*)d_in[0];   // [B, F, T]
    const float* W = (const float*)d_in[1];   // [F, U]
    float* out = (float*)d_out;               // [B, T, U] float32

    cudaFuncSetAttribute(snn_mma_kernel,
                         cudaFuncAttributeMaxDynamicSharedMemorySize, SMEM_TOTAL);

    dim3 gx(KP * (T_ / 4) / 256, B_);         // 104 x 256
    split_x_stream<<<gx, 256>>>(x);
    dim3 gw(KP / 32, U_ / 32);                // 26 x 64
    split_w_kernel<<<gw, dim3(32, 8)>>>(W);

    dim3 grid(U_ / NT, B_);                   // 16 x 256 = 4096 CTAs
    snn_mma_kernel<<<grid, 512, SMEM_TOTAL>>>(out);
}

// round 15
// speedup vs baseline: 1.0063x; 1.0063x over previous
#include <cuda_runtime.h>
#include <cuda_fp16.h>
#include <cstdint>
#include <cstddef>

// ---------------- problem shape ----------------
#define B_  256
#define F_  784
#define T_  128
#define U_  2048
#define KP  832            // K padded to 13*64 (zeros beyond 784 contribute 0)
#define KC  64             // k per chunk
#define NCH 13             // KP/KC
#define NT  64             // u-tile per CTA (2 CTAs/SM)

#define ALPHA_  0.9f
#define BETA_   0.85f
#define THRESH_ 1.0f
#define SPLIT_SCALE 2048.0f
#define INV_SCALE (1.0f / 2048.0f)

// smem stage: A0,A1: [128 t rows][72 halfs] (64 k data + 8 pad) = 18432 B each
//             B0,B1: [ 64 u rows][72 halfs]                    =  9216 B each
#define ROWH    72
#define ARR_A   (128 * ROWH * 2)      // 18432
#define ARR_Bb  (64 * ROWH * 2)       // 9216
#define BOFF    (2 * ARR_A)           // 36864
#define STAGE_B (2 * ARR_A + 2 * ARR_Bb)  // 55296
#define SMEM_TOTAL (2 * STAGE_B)      // 110592 -> 2 CTAs/SM (216KB < 228KB)

// ---------------- scratch (device globals; allocation-free rule) ----------
__device__ __half X0d[B_][T_][KP];    // 54.5 MB  main split of x, K-major
__device__ __half X1d[B_][T_][KP];    // 54.5 MB  residual*2048
__device__ __half W0d[U_][KP];        // 3.4 MB
__device__ __half W1d[U_][KP];        // 3.4 MB

// ---------------- PTX helpers (all baseline sm_80 ISA -> compute_103 OK) ---
__device__ __forceinline__ void cp_async16(uint32_t saddr, const void* g) {
    asm volatile("cp.async.cg.shared.global [%0], [%1], 16;"
                 :: "r"(saddr), "l"(g) : "memory");
}
__device__ __forceinline__ void cp_commit() {
    asm volatile("cp.async.commit_group;" ::: "memory");
}
__device__ __forceinline__ void cp_wait1() {
    asm volatile("cp.async.wait_group 1;" ::: "memory");
}
__device__ __forceinline__ void cp_wait0() {
    asm volatile("cp.async.wait_group 0;" ::: "memory");
}
// plain (non-trans) ldmatrix x4: lane l gets M[l/4][2*(l%4)..+1] per 8x8 mat.
__device__ __forceinline__ void ldsm4(uint32_t* r, uint32_t addr) {
    asm volatile("ldmatrix.sync.aligned.m8n8.x4.shared.b16 {%0,%1,%2,%3}, [%4];"
                 : "=r"(r[0]), "=r"(r[1]), "=r"(r[2]), "=r"(r[3]) : "r"(addr));
}
__device__ __forceinline__ void mma16816(float* c, const uint32_t* a, const uint32_t* b) {
    asm volatile(
        "mma.sync.aligned.m16n8k16.row.col.f32.f16.f16.f32 "
        "{%0,%1,%2,%3}, {%4,%5,%6,%7}, {%8,%9}, {%0,%1,%2,%3};"
        : "+f"(c[0]), "+f"(c[1]), "+f"(c[2]), "+f"(c[3])
        : "r"(a[0]), "r"(a[1]), "r"(a[2]), "r"(a[3]), "r"(b[0]), "r"(b[1]));
}
// packed fp16x2 multiply (exact for power-of-two scales)
__device__ __forceinline__ uint32_t hmul2(uint32_t a, uint32_t s) {
    uint32_t d;
    asm("mul.f16x2 %0, %1, %2;" : "=r"(d) : "r"(a), "r"(s));
    return d;
}
#define SCALE_A_2M5 0x28002800u   // half2(2^-5, 2^-5)
#define SCALE_B_2M6 0x24002400u   // half2(2^-6, 2^-6)
__device__ __forceinline__ uint32_t s2u(const void* p) {
    return (uint32_t)__cvta_generic_to_shared(p);
}

// ---------------- split precompute (R11 versions, bit-exact) --------------
__global__ void split_x_kernel(const float* __restrict__ x) {
    __shared__ float tile[32][33];
    const int b  = blockIdx.z;
    const int f0 = blockIdx.x * 32;
    const int t0 = blockIdx.y * 32;
    const int tx = threadIdx.x, ty = threadIdx.y;
    const int tid = ty * 32 + tx;
    for (int i = ty; i < 32; i += 8) {
        const int f = f0 + i;
        float v = 0.f;
        if (f < F_) v = x[((size_t)b * F_ + f) * T_ + t0 + tx];
        tile[i][tx] = v;
    }
    __syncthreads();
    for (int idx = tid; idx < 32 * 16; idx += 256) {
        const int i = idx >> 4;           // t row 0..31
        const int j = idx & 15;           // f pair 0..15
        const int t = t0 + i;
        const int f = f0 + 2 * j;
        const float v0 = tile[2 * j][i];
        const float v1 = tile[2 * j + 1][i];
        const __half h0a = __float2half_rn(v0);
        const __half h1a = __float2half_rn((v0 - __half2float(h0a)) * SPLIT_SCALE);
        const __half h0b = __float2half_rn(v1);
        const __half h1b = __float2half_rn((v1 - __half2float(h0b)) * SPLIT_SCALE);
        *(__half2*)&X0d[b][t][f] = __halves2half2(h0a, h0b);
        *(__half2*)&X1d[b][t][f] = __halves2half2(h1a, h1b);
    }
}
__global__ void split_w_kernel(const float* __restrict__ W) {
    __shared__ float tile[32][33];
    const int f0 = blockIdx.x * 32;
    const int u0 = blockIdx.y * 32;
    const int tx = threadIdx.x, ty = threadIdx.y;
    const int tid = ty * 32 + tx;
    for (int i = ty; i < 32; i += 8) {
        const int f = f0 + i;
        float v = 0.f;
        if (f < F_) v = W[(size_t)f * U_ + u0 + tx];
        tile[i][tx] = v;
    }
    __syncthreads();
    for (int idx = tid; idx < 32 * 16; idx += 256) {
        const int i = idx >> 4;           // u row
        const int j = idx & 15;           // f pair
        const int u = u0 + i;
        const int f = f0 + 2 * j;
        const float v0 = tile[2 * j][i];
        const float v1 = tile[2 * j + 1][i];
        const __half h0a = __float2half_rn(v0);
        const __half h1a = __float2half_rn((v0 - __half2float(h0a)) * SPLIT_SCALE);
        const __half h0b = __float2half_rn(v1);
        const __half h1b = __float2half_rn((v1 - __half2float(h0b)) * SPLIT_SCALE);
        *(__half2*)&W0d[u][f] = __halves2half2(h0a, h0b);
        *(__half2*)&W1d[u][f] = __halves2half2(h1a, h1b);
    }
}

// ---------------- chunk loader: 12 cp.async16 per thread ----------------
// Row = 64 data halfs = 128 B = EIGHT 16B units (c in 0..7).
__device__ __forceinline__ void load_chunk(uint32_t sb, int stage, int p,
                                           int b, int u0, int tid) {
    const uint32_t st = sb + stage * STAGE_B;
    const int k0 = p * KC;
    // A arrays: 128 rows x 8 units = 1024 units -> 4 per thread per array
#pragma unroll
    for (int q = 0; q < 2; ++q) {
        const __half* src = q ? &X1d[b][0][k0] : &X0d[b][0][k0];
#pragma unroll
        for (int i = 0; i < 4; ++i) {
            const int u_  = tid + 256 * i;       // 0..1023
            const int row = u_ >> 3;             // t row 0..127
            const int c   = u_ & 7;              // 16B unit (k)
            cp_async16(st + q * ARR_A + row * (ROWH * 2) + c * 16,
                       (const char*)src + (size_t)row * (KP * 2) + c * 16);
        }
    }
    // B arrays: 64 rows x 8 units = 512 units -> 2 per thread per array
#pragma unroll
    for (int q = 0; q < 2; ++q) {
        const __half* src = q ? &W1d[u0][k0] : &W0d[u0][k0];
#pragma unroll
        for (int i = 0; i < 2; ++i) {
            const int u_  = tid + 256 * i;       // 0..511
            const int row = u_ >> 3;             // u row 0..63
            const int c   = u_ & 7;
            cp_async16(st + BOFF + q * ARR_Bb + row * (ROWH * 2) + c * 16,
                       (const char*)src + (size_t)row * (KP * 2) + c * 16);
        }
    }
}

// ---------------- fused mma.sync GEMM + LIF scan ----------------
// 8 warps, warp tile m16 x n64 (m0 = wid*16, full NT=64 n-range).
// Per-accumulator k16 order ascending, term order (a0b0; a0b1,a1b0,a1m*b1m)
// unchanged -> bit-identical to R11 (rel_err must be exactly 0.000991695).
__global__ __launch_bounds__(256, 2)
void snn_mma_kernel(float* __restrict__ out)
{
    extern __shared__ __align__(128) char smem[];
    const uint32_t sb = s2u(smem);
    const int tid = threadIdx.x;
    const int wid = tid >> 5;
    const int lid = tid & 31;
    const int u0  = blockIdx.x * NT;
    const int b   = blockIdx.y;
    const int m0  = wid * 16;                 // warp's t rows

    // accumulators: 8 n-tiles x 4 regs, two sets
    float acc0[32], acc1[32];
#pragma unroll
    for (int i = 0; i < 32; ++i) { acc0[i] = 0.f; acc1[i] = 0.f; }

    // ldmatrix lane addressing (R11 scheme)
    const int ar = m0 + (lid & 15);           // A row
    const int ac = (lid >> 4) & 1;            // k col-half
    const int brbase = (lid & 7) + ((lid & 16) ? 8 : 0);
    const int bc = (lid >> 3) & 1;

    load_chunk(sb, 0, 0, b, u0, tid);
    cp_commit();

    for (int p = 0; p < NCH; ++p) {
        const int s = p & 1;
        if (p + 1 < NCH) { load_chunk(sb, s ^ 1, p + 1, b, u0, tid); cp_commit(); }
        if (p + 1 < NCH) cp_wait1(); else cp_wait0();   // chunk p landed (mine)
        __syncthreads();                                 // everyone's landed

        const uint32_t st = sb + s * STAGE_B;
#pragma unroll
        for (int ks = 0; ks < 4; ++ks) {                 // four k16 steps
            uint32_t a0f[4], a1f[4], a1m[4];
            const uint32_t aoff = st + ar * (ROWH * 2) + ks * 32 + ac * 16;
            ldsm4(a0f, aoff);                            // A0
            ldsm4(a1f, aoff + ARR_A);                    // A1 (residual*2048)
#pragma unroll
            for (int i = 0; i < 4; ++i) a1m[i] = hmul2(a1f[i], SCALE_A_2M5);
#pragma unroll
            for (int j = 0; j < 4; ++j) {                // 4 n-pairs (NT=64)
                uint32_t b0f[4], b1f[4], b1m[4];
                const uint32_t boff = st + BOFF
                    + (j * 16 + brbase) * (ROWH * 2) + ks * 32 + bc * 16;
                ldsm4(b0f, boff);                        // W0
                ldsm4(b1f, boff + ARR_Bb);               // W1 (residual*2048)
#pragma unroll
                for (int i = 0; i < 4; ++i) b1m[i] = hmul2(b1f[i], SCALE_B_2M6);
                float* c0a = acc0 + (2 * j) * 4;
                float* c1a = acc1 + (2 * j) * 4;
                float* c0b = acc0 + (2 * j + 1) * 4;
                float* c1b = acc1 + (2 * j + 1) * 4;
                // n-tile 2j (frag regs [0],[1])
                mma16816(c0a, a0f, b0f);
                mma16816(c1a, a0f, b1f);
                mma16816(c1a, a1f, b0f);
                mma16816(c1a, a1m, b1m);
                // n-tile 2j+1 (frag regs [2],[3])
                mma16816(c0b, a0f, b0f + 2);
                mma16816(c1b, a0f, b1f + 2);
                mma16816(c1b, a1f, b0f + 2);
                mma16816(c1b, a1m, b1m + 2);
            }
        }
        if (p + 1 < NCH) __syncthreads();   // stage s reads done before iter p+1
    }

    // ---- epilogue: combine splits, park h in smem (aliases stages) ----
    __syncthreads();
    float* Cs = (float*)smem;               // [128][68] padded rows
    const int g  = lid >> 2;
    const int c2 = (lid & 3) * 2;
#pragma unroll
    for (int nt = 0; nt < 8; ++nt) {
        const int col = nt * 8 + c2;
        const float* p0 = acc0 + nt * 4;
        const float* p1 = acc1 + nt * 4;
        float2 v0 = { p0[0] + p1[0] * INV_SCALE, p0[1] + p1[1] * INV_SCALE };
        float2 v1 = { p0[2] + p1[2] * INV_SCALE, p0[3] + p1[3] * INV_SCALE };
        *(float2*)&Cs[(m0 + g) * 68 + col]     = v0;
        *(float2*)&Cs[(m0 + g + 8) * 68 + col] = v1;
    }
    __syncthreads();

    // ---- LIF scan over t; thread = u column (threads 0..63) ----
    if (tid < NT) {
        float* op = out + (size_t)b * T_ * U_ + u0 + tid;
        float syn = 0.f, mem = 0.f;
#pragma unroll 4
        for (int t = 0; t < T_; ++t) {
            const float h = Cs[t * 68 + tid];
            syn = ALPHA_ * syn + h;           // synaptic current decay
            mem = BETA_  * mem + syn;         // membrane decay
            const float spk = (mem - THRESH_ > 0.f) ? 1.f : 0.f;
            mem -= spk * THRESH_;             // soft reset
            op[(size_t)t * U_] = spk;
        }
    }
}

// ---------------- launch ----------------
extern "C" void kernel_launch(void* const* d_in, const int* in_sizes, int n_in,
                              void* d_out, int out_size) {
    (void)in_sizes; (void)n_in; (void)out_size;
    const float* x = (const float*)d_in[0];   // [B, F, T]
    const float* W = (const float*)d_in[1];   // [F, U]
    float* out = (float*)d_out;               // [B, T, U] float32

    cudaFuncSetAttribute(snn_mma_kernel,
                         cudaFuncAttributeMaxDynamicSharedMemorySize, SMEM_TOTAL);

    dim3 gx(KP / 32, T_ / 32, B_);            // 26 x 4 x 256
    split_x_kernel<<<gx, dim3(32, 8)>>>(x);
    dim3 gw(KP / 32, U_ / 32);                // 26 x 64
    split_w_kernel<<<gw, dim3(32, 8)>>>(W);

    dim3 grid(U_ / NT, B_);                   // 32 x 256 = 8192 CTAs
    snn_mma_kernel<<<grid, 256, SMEM_TOTAL>>>(out);
}